// round 3
// baseline (speedup 1.0000x reference)
#include <cuda_runtime.h>
#include <math.h>

#define TPB 128                 // threads per block == tokens per block
#define PC_STRIDE 133           // 132 + 1 pad; 133 mod 32 = 5 (coprime) -> conflict-free
#define NEG_INF (-3.402823466e+38f)

// dynamic smem layout (floats):
//   sPC  : TPB * 133            = 17024
//   sW1T : 64 * 20 (transposed) =  1280   (16B-aligned rows: 20 floats = 80B)
//   sB1  : 64
//   sW2  : 64
//   sQ   : TPB
#define SM_PC    0
#define SM_W1T   (TPB * PC_STRIDE)
#define SM_B1    (SM_W1T + 1280)
#define SM_W2    (SM_B1 + 64)
#define SM_Q     (SM_W2 + 64)
#define SM_TOTAL (SM_Q + TPB)

__global__ __launch_bounds__(TPB) void dfine_lqe_kernel(
    const float* __restrict__ scores,   // (tokens, 80)
    const float* __restrict__ pc,       // (tokens, 132)
    const float* __restrict__ W1,       // (20, 64)
    const float* __restrict__ b1,       // (64,)
    const float* __restrict__ W2,       // (64, 1)
    const float* __restrict__ b2,       // (1,)
    float* __restrict__ out,            // (tokens, 80)
    int tokens)
{
    extern __shared__ float sm[];
    float* sPC  = sm + SM_PC;
    float* sW1T = sm + SM_W1T;
    float* sB1  = sm + SM_B1;
    float* sW2  = sm + SM_W2;
    float* sQ   = sm + SM_Q;

    const int tid = threadIdx.x;
    const int t0  = blockIdx.x * TPB;
    const int ntb = min(TPB, tokens - t0);   // tokens in this block (guard)

    // ---- stage weights (transpose W1 -> [j][d]) ----
    #pragma unroll 2
    for (int i = tid; i < 1280; i += TPB) {
        int d = i % 20;
        int j = i / 20;
        sW1T[i] = W1[d * 64 + j];
    }
    if (tid < 64) {
        sB1[tid] = b1[tid];
        sW2[tid] = W2[tid];
    }

    // ---- stage pred_corners tile, coalesced float4 ----
    {
        const float4* pc4 = reinterpret_cast<const float4*>(pc) + (size_t)t0 * 33;
        const int nvec = ntb * 33;
        for (int i = tid; i < nvec; i += TPB) {
            float4 v = pc4[i];
            int row = i / 33;
            int c   = i - row * 33;
            float* dst = &sPC[row * PC_STRIDE + c * 4];
            dst[0] = v.x; dst[1] = v.y; dst[2] = v.z; dst[3] = v.w;
        }
    }
    __syncthreads();

    // ---- per-token compute (one thread per token) ----
    if (tid < ntb) {
        const float* x = &sPC[tid * PC_STRIDE];
        float stat[20];

        for (int g = 0; g < 4; g++) {
            const float* xg = x + g * 33;
            // branchless running top-4 (descending): m0>=m1>=m2>=m3
            float m0 = NEG_INF, m1 = NEG_INF, m2 = NEG_INF, m3 = NEG_INF;
            #pragma unroll
            for (int k = 0; k < 33; k++) {
                float v  = xg[k];
                float v1 = fminf(m0, v);  m0 = fmaxf(m0, v);
                float v2 = fminf(m1, v1); m1 = fmaxf(m1, v1);
                float v3 = fminf(m2, v2); m2 = fmaxf(m2, v2);
                m3 = fmaxf(m3, v3);
            }
            // softmax denominator (m0 is the true max)
            float s = 0.0f;
            #pragma unroll
            for (int k = 0; k < 33; k++) s += __expf(xg[k] - m0);
            float inv = 1.0f / s;
            float p0 = inv;                     // exp(m0 - m0) = 1
            float p1 = __expf(m1 - m0) * inv;
            float p2 = __expf(m2 - m0) * inv;
            float p3 = __expf(m3 - m0) * inv;
            stat[g * 5 + 0] = p0;
            stat[g * 5 + 1] = p1;
            stat[g * 5 + 2] = p2;
            stat[g * 5 + 3] = p3;
            stat[g * 5 + 4] = 0.25f * (p0 + p1 + p2 + p3);
        }

        // tiny MLP: q = W2 . relu(W1^T stat + b1) + b2
        float q = b2[0];
        #pragma unroll 4
        for (int j = 0; j < 64; j++) {
            const float4* w4 = reinterpret_cast<const float4*>(&sW1T[j * 20]);
            float acc = sB1[j];
            float4 wa = w4[0], wb = w4[1], wc = w4[2], wd = w4[3], we = w4[4];
            acc = fmaf(stat[0],  wa.x, acc); acc = fmaf(stat[1],  wa.y, acc);
            acc = fmaf(stat[2],  wa.z, acc); acc = fmaf(stat[3],  wa.w, acc);
            acc = fmaf(stat[4],  wb.x, acc); acc = fmaf(stat[5],  wb.y, acc);
            acc = fmaf(stat[6],  wb.z, acc); acc = fmaf(stat[7],  wb.w, acc);
            acc = fmaf(stat[8],  wc.x, acc); acc = fmaf(stat[9],  wc.y, acc);
            acc = fmaf(stat[10], wc.z, acc); acc = fmaf(stat[11], wc.w, acc);
            acc = fmaf(stat[12], wd.x, acc); acc = fmaf(stat[13], wd.y, acc);
            acc = fmaf(stat[14], wd.z, acc); acc = fmaf(stat[15], wd.w, acc);
            acc = fmaf(stat[16], we.x, acc); acc = fmaf(stat[17], we.y, acc);
            acc = fmaf(stat[18], we.z, acc); acc = fmaf(stat[19], we.w, acc);
            q = fmaf(fmaxf(acc, 0.0f), sW2[j], q);
        }
        sQ[tid] = q;
    }
    __syncthreads();

    // ---- coalesced epilogue: out = scores + q[token], float4 ----
    {
        const float4* sc4  = reinterpret_cast<const float4*>(scores) + (size_t)t0 * 20;
        float4*       out4 = reinterpret_cast<float4*>(out) + (size_t)t0 * 20;
        const int nvec = ntb * 20;
        for (int i = tid; i < nvec; i += TPB) {
            int row = i / 20;
            float4 s = sc4[i];
            float qq = sQ[row];
            s.x += qq; s.y += qq; s.z += qq; s.w += qq;
            out4[i] = s;
        }
    }
}

extern "C" void kernel_launch(void* const* d_in, const int* in_sizes, int n_in,
                              void* d_out, int out_size)
{
    const float* scores = (const float*)d_in[0];
    const float* pc     = (const float*)d_in[1];
    const float* W1     = (const float*)d_in[2];
    const float* b1     = (const float*)d_in[3];
    const float* W2     = (const float*)d_in[4];
    const float* b2     = (const float*)d_in[5];
    float* out = (float*)d_out;

    const int tokens = in_sizes[1] / 132;      // (B*L)
    const int nblocks = (tokens + TPB - 1) / TPB;
    const size_t smem = SM_TOTAL * sizeof(float);

    static bool attr_set = false;
    if (!attr_set) {
        cudaFuncSetAttribute(dfine_lqe_kernel,
                             cudaFuncAttributeMaxDynamicSharedMemorySize,
                             (int)smem);
        attr_set = true;
    }

    dfine_lqe_kernel<<<nblocks, TPB, smem>>>(scores, pc, W1, b1, W2, b2, out, tokens);
}

// round 4
// speedup vs baseline: 1.4926x; 1.4926x over previous
#include <cuda_runtime.h>
#include <math.h>

#define TPB 128
#define NEG_INF (-3.402823466e+38f)

__global__ __launch_bounds__(TPB) void dfine_lqe_kernel(
    const float* __restrict__ scores,   // (tokens, 80)
    const float* __restrict__ pc,       // (tokens, 132)
    const float* __restrict__ W1,       // (20, 64)
    const float* __restrict__ b1,       // (64,)
    const float* __restrict__ W2,       // (64, 1)
    const float* __restrict__ b2,       // (1,)
    float* __restrict__ out,            // (tokens, 80)
    int tokens)
{
    __shared__ float sW1T[1280];   // transposed: [j][d], rows of 20 floats (80B, 16B-aligned)
    __shared__ float sB1[64];
    __shared__ float sW2[64];
    __shared__ float sQ[TPB];

    const int tid = threadIdx.x;
    const int t0  = blockIdx.x * TPB;
    const int ntb = min(TPB, tokens - t0);

    // ---- stage weights (transpose W1 -> [j][d]) ----
    #pragma unroll 2
    for (int i = tid; i < 1280; i += TPB) {
        int d = i % 20;
        int j = i / 20;
        sW1T[i] = W1[d * 64 + j];
    }
    if (tid < 64) {
        sB1[tid] = b1[tid];
        sW2[tid] = W2[tid];
    }
    __syncthreads();

    // ---- per-token compute: corners streamed global -> registers ----
    if (tid < ntb) {
        const int token = t0 + tid;
        const float4* xp4 = reinterpret_cast<const float4*>(pc) + (size_t)token * 33;
        float stat[20];

        #pragma unroll
        for (int g = 0; g < 4; g++) {
            // group g = elements [g*33, g*33+33). Aligned float4 window:
            // base = floor(g*33/4) in {0,8,16,24}; offset within window = g.
            const int base = (g * 33) >> 2;
            float buf[36];
            #pragma unroll
            for (int i = 0; i < 9; i++) {
                float4 v = xp4[base + i];
                buf[i * 4 + 0] = v.x;
                buf[i * 4 + 1] = v.y;
                buf[i * 4 + 2] = v.z;
                buf[i * 4 + 3] = v.w;
            }
            // branchless running top-4 (descending) over buf[g .. g+32]
            float m0 = NEG_INF, m1 = NEG_INF, m2 = NEG_INF, m3 = NEG_INF;
            #pragma unroll
            for (int k = 0; k < 33; k++) {
                float v  = buf[g + k];
                float v1 = fminf(m0, v);  m0 = fmaxf(m0, v);
                float v2 = fminf(m1, v1); m1 = fmaxf(m1, v1);
                float v3 = fminf(m2, v2); m2 = fmaxf(m2, v2);
                m3 = fmaxf(m3, v3);
            }
            // softmax denominator (m0 = true max)
            float s = 0.0f;
            #pragma unroll
            for (int k = 0; k < 33; k++) s += __expf(buf[g + k] - m0);
            float inv = 1.0f / s;
            float p0 = inv;
            float p1 = __expf(m1 - m0) * inv;
            float p2 = __expf(m2 - m0) * inv;
            float p3 = __expf(m3 - m0) * inv;
            stat[g * 5 + 0] = p0;
            stat[g * 5 + 1] = p1;
            stat[g * 5 + 2] = p2;
            stat[g * 5 + 3] = p3;
            stat[g * 5 + 4] = 0.25f * (p0 + p1 + p2 + p3);
        }

        // tiny MLP: q = W2 . relu(W1^T stat + b1) + b2
        float q = b2[0];
        #pragma unroll 4
        for (int j = 0; j < 64; j++) {
            const float4* w4 = reinterpret_cast<const float4*>(&sW1T[j * 20]);
            float acc = sB1[j];
            float4 wa = w4[0], wb = w4[1], wc = w4[2], wd = w4[3], we = w4[4];
            acc = fmaf(stat[0],  wa.x, acc); acc = fmaf(stat[1],  wa.y, acc);
            acc = fmaf(stat[2],  wa.z, acc); acc = fmaf(stat[3],  wa.w, acc);
            acc = fmaf(stat[4],  wb.x, acc); acc = fmaf(stat[5],  wb.y, acc);
            acc = fmaf(stat[6],  wb.z, acc); acc = fmaf(stat[7],  wb.w, acc);
            acc = fmaf(stat[8],  wc.x, acc); acc = fmaf(stat[9],  wc.y, acc);
            acc = fmaf(stat[10], wc.z, acc); acc = fmaf(stat[11], wc.w, acc);
            acc = fmaf(stat[12], wd.x, acc); acc = fmaf(stat[13], wd.y, acc);
            acc = fmaf(stat[14], wd.z, acc); acc = fmaf(stat[15], wd.w, acc);
            acc = fmaf(stat[16], we.x, acc); acc = fmaf(stat[17], we.y, acc);
            acc = fmaf(stat[18], we.z, acc); acc = fmaf(stat[19], we.w, acc);
            q = fmaf(fmaxf(acc, 0.0f), sW2[j], q);
        }
        sQ[tid] = q;
    }
    __syncthreads();

    // ---- coalesced epilogue: out = scores + q[token], float4 ----
    {
        const float4* sc4  = reinterpret_cast<const float4*>(scores) + (size_t)t0 * 20;
        float4*       out4 = reinterpret_cast<float4*>(out) + (size_t)t0 * 20;
        const int nvec = ntb * 20;
        #pragma unroll 4
        for (int i = tid; i < nvec; i += TPB) {
            int row = i / 20;
            float4 s = sc4[i];
            float qq = sQ[row];
            s.x += qq; s.y += qq; s.z += qq; s.w += qq;
            out4[i] = s;
        }
    }
}

extern "C" void kernel_launch(void* const* d_in, const int* in_sizes, int n_in,
                              void* d_out, int out_size)
{
    const float* scores = (const float*)d_in[0];
    const float* pc     = (const float*)d_in[1];
    const float* W1     = (const float*)d_in[2];
    const float* b1     = (const float*)d_in[3];
    const float* W2     = (const float*)d_in[4];
    const float* b2     = (const float*)d_in[5];
    float* out = (float*)d_out;

    const int tokens = in_sizes[1] / 132;
    const int nblocks = (tokens + TPB - 1) / TPB;

    dfine_lqe_kernel<<<nblocks, TPB>>>(scores, pc, W1, b1, W2, b2, out, tokens);
}